// round 3
// baseline (speedup 1.0000x reference)
#include <cuda_runtime.h>
#include <cuda_bf16.h>
#include <cstdint>

// ============================================================================
// Problem constants (shapes fixed by setup_inputs: N=M=8192, D=128)
// ============================================================================
#define DV      128
#define MAXROWS 8192
#define TILE    128

// bf16 copies + fp32 squared norms (device-global scratch; allowed)
__device__ __nv_bfloat16 g_anc_bf[MAXROWS * DV];
__device__ __nv_bfloat16 g_pn_bf[MAXROWS * DV];
__device__ float         g_anc2[MAXROWS];
__device__ float         g_pn2[MAXROWS];

// ============================================================================
// Kernel 1: fp32 -> bf16 conversion + exact fp32 squared row norms.
// One warp per row (128 floats = 32 lanes x float4).
// ============================================================================
__global__ void prep_kernel(const float* __restrict__ anc, const float* __restrict__ pn,
                            int N, int M) {
    int warp = (blockIdx.x * blockDim.x + threadIdx.x) >> 5;
    int lane = threadIdx.x & 31;
    if (warp >= N + M) return;

    const float* src;
    __nv_bfloat16* dst;
    float* nrm;
    int row;
    if (warp < N) { row = warp;     src = anc + (size_t)row * DV; dst = g_anc_bf + (size_t)row * DV; nrm = g_anc2; }
    else          { row = warp - N; src = pn  + (size_t)row * DV; dst = g_pn_bf  + (size_t)row * DV; nrm = g_pn2;  }

    float4 v = reinterpret_cast<const float4*>(src)[lane];
    float s = v.x * v.x + v.y * v.y + v.z * v.z + v.w * v.w;

    __nv_bfloat162 p0 = __floats2bfloat162_rn(v.x, v.y);
    __nv_bfloat162 p1 = __floats2bfloat162_rn(v.z, v.w);
    reinterpret_cast<__nv_bfloat162*>(dst)[lane * 2 + 0] = p0;
    reinterpret_cast<__nv_bfloat162*>(dst)[lane * 2 + 1] = p1;

    #pragma unroll
    for (int o = 16; o; o >>= 1) s += __shfl_xor_sync(0xFFFFFFFFu, s, o);
    if (lane == 0) nrm[row] = s;
}

// ============================================================================
// Kernel 2: 128x128 output tile per CTA via mma.sync (HMMA bf16, fp32 accum).
// (tcgen05 is rejected by this toolchain: PTX .target is base sm_103.)
//
// - 256 threads = 8 warps in a 4(m) x 2(n) grid; each warp owns a 32x64
//   sub-tile = 2 m16 x 8 n8 mma tiles; K=128 fully unrolled (8 k16 steps).
// - A tile = z_anc rows (output rows i), B tile = z_pos_neg rows (output
//   cols j); B is "col-major" operand by construction since mma wants B^T.
// - SMEM strides padded (136 bf16) -> conflict-free fragment loads.
// - Epilogue: fuse -sqrt(max(a2+b2-2ab,0)) in regs, stage the fp32 tile in
//   SMEM (reusing operand space), then fully-coalesced float4 stores.
// ============================================================================
#define SAS 136                              // bf16 elems per SMEM row (128+8 pad)
static constexpr uint32_t SM_A     = 0;                    // 128*136*2 = 34816
static constexpr uint32_t SM_B     = 34816;                // 34816
static constexpr uint32_t SM_A2    = 69632;                // 512 B
static constexpr uint32_t SM_B2    = 70144;                // 512 B
static constexpr uint32_t SMEM_BYTES = 70656;
#define EST 132                              // fp32 elems per epilogue SMEM row

__device__ __forceinline__ void mma_bf16(float* c, const uint32_t* a, const uint32_t* b) {
    asm volatile(
        "mma.sync.aligned.m16n8k16.row.col.f32.bf16.bf16.f32 "
        "{%0,%1,%2,%3}, {%4,%5,%6,%7}, {%8,%9}, {%0,%1,%2,%3};"
        : "+f"(c[0]), "+f"(c[1]), "+f"(c[2]), "+f"(c[3])
        : "r"(a[0]), "r"(a[1]), "r"(a[2]), "r"(a[3]), "r"(b[0]), "r"(b[1]));
}

__global__ void __launch_bounds__(256, 2) gemm_kernel(float* __restrict__ out, int N, int M) {
    extern __shared__ char smem[];

    const int tid    = threadIdx.x;
    const int lid    = tid & 31;
    const int wid    = tid >> 5;
    const int warp_m = wid & 3;       // 0..3 -> m offset 32*warp_m
    const int warp_n = wid >> 2;      // 0..1 -> n offset 64*warp_n
    const int tj     = blockIdx.x;    // output col tile (pn rows)
    const int ti     = blockIdx.y;    // output row tile (anc rows)

    // ---- Global -> SMEM: 128 rows x 256 B each, padded stride ----
    {
        const uint4* gA = reinterpret_cast<const uint4*>(g_anc_bf + (size_t)ti * TILE * DV);
        const uint4* gB = reinterpret_cast<const uint4*>(g_pn_bf  + (size_t)tj * TILE * DV);
        int c0 = tid & 15;            // uint4 column 0..15
        int r0 = tid >> 4;            // row 0..15
        #pragma unroll
        for (int it = 0; it < 8; it++) {
            int r = r0 + it * 16;
            uint32_t so = (uint32_t)(r * (SAS * 2) + c0 * 16);
            *reinterpret_cast<uint4*>(smem + SM_A + so) = gA[r * 16 + c0];
            *reinterpret_cast<uint4*>(smem + SM_B + so) = gB[r * 16 + c0];
        }
        // norms
        reinterpret_cast<float*>(smem + SM_A2)[tid >> 1] = g_anc2[ti * TILE + (tid >> 1)]; // 2x redundant, harmless
        reinterpret_cast<float*>(smem + SM_B2)[tid >> 1] = g_pn2[tj * TILE + (tid >> 1)];
    }
    __syncthreads();

    // ---- Mainloop: K = 8 x k16 ----
    float acc[2][8][4];
    #pragma unroll
    for (int mt = 0; mt < 2; mt++)
        #pragma unroll
        for (int nt = 0; nt < 8; nt++)
            #pragma unroll
            for (int e = 0; e < 4; e++) acc[mt][nt][e] = 0.0f;

    const char* sA = smem + SM_A;
    const char* sB = smem + SM_B;
    const int arow = warp_m * 32 + (lid >> 2);      // fragment base row within tile
    const int bcol = warp_n * 64 + (lid >> 2);      // fragment base col
    const int kbyt = (lid & 3) * 4;                 // k-pair byte offset within k16

    #pragma unroll
    for (int ks = 0; ks < 8; ks++) {
        const int kb = ks * 32 + kbyt;              // k byte base (16 bf16 = 32B per step)

        uint32_t afr[2][4];
        #pragma unroll
        for (int mt = 0; mt < 2; mt++) {
            const char* base = sA + (size_t)(arow + mt * 16) * (SAS * 2) + kb;
            afr[mt][0] = *reinterpret_cast<const uint32_t*>(base);
            afr[mt][1] = *reinterpret_cast<const uint32_t*>(base + 8 * (SAS * 2));
            afr[mt][2] = *reinterpret_cast<const uint32_t*>(base + 16);
            afr[mt][3] = *reinterpret_cast<const uint32_t*>(base + 8 * (SAS * 2) + 16);
        }
        uint32_t bfr[8][2];
        #pragma unroll
        for (int nt = 0; nt < 8; nt++) {
            const char* base = sB + (size_t)(bcol + nt * 8) * (SAS * 2) + kb;
            bfr[nt][0] = *reinterpret_cast<const uint32_t*>(base);
            bfr[nt][1] = *reinterpret_cast<const uint32_t*>(base + 16);
        }
        #pragma unroll
        for (int mt = 0; mt < 2; mt++)
            #pragma unroll
            for (int nt = 0; nt < 8; nt++)
                mma_bf16(acc[mt][nt], afr[mt], bfr[nt]);
    }

    // ---- Epilogue: fuse norms + sqrt in regs, stage via SMEM, coalesced STG ----
    const float* a2s = reinterpret_cast<const float*>(smem + SM_A2);
    const float* b2s = reinterpret_cast<const float*>(smem + SM_B2);

    __syncthreads();                    // operand tiles dead; reuse as fp32 tile
    float* st = reinterpret_cast<float*>(smem);

    #pragma unroll
    for (int mt = 0; mt < 2; mt++) {
        #pragma unroll
        for (int nt = 0; nt < 8; nt++) {
            int r  = warp_m * 32 + mt * 16 + (lid >> 2);
            int cc = warp_n * 64 + nt * 8 + (lid & 3) * 2;
            float a2r0 = a2s[r], a2r8 = a2s[r + 8];
            float b2c0 = b2s[cc], b2c1 = b2s[cc + 1];
            float v, q;
            v = fmaxf(a2r0 + b2c0 - 2.0f * acc[mt][nt][0], 0.0f);
            asm("sqrt.approx.f32 %0, %1;" : "=f"(q) : "f"(v));
            st[r * EST + cc] = -q;
            v = fmaxf(a2r0 + b2c1 - 2.0f * acc[mt][nt][1], 0.0f);
            asm("sqrt.approx.f32 %0, %1;" : "=f"(q) : "f"(v));
            st[r * EST + cc + 1] = -q;
            v = fmaxf(a2r8 + b2c0 - 2.0f * acc[mt][nt][2], 0.0f);
            asm("sqrt.approx.f32 %0, %1;" : "=f"(q) : "f"(v));
            st[(r + 8) * EST + cc] = -q;
            v = fmaxf(a2r8 + b2c1 - 2.0f * acc[mt][nt][3], 0.0f);
            asm("sqrt.approx.f32 %0, %1;" : "=f"(q) : "f"(v));
            st[(r + 8) * EST + cc + 1] = -q;
        }
    }
    __syncthreads();

    // Coalesced write-out: each row = 32 float4 = 512B dense per warp-instr
    float* outp = out + (size_t)(ti * TILE) * M + tj * TILE;
    int c4 = tid & 31;                  // float4 col 0..31
    int r0 = tid >> 5;                  // row 0..7
    #pragma unroll
    for (int it = 0; it < 16; it++) {
        int r = r0 + it * 8;
        float4 v = *reinterpret_cast<const float4*>(st + r * EST + c4 * 4);
        *reinterpret_cast<float4*>(outp + (size_t)r * M + c4 * 4) = v;
    }
}

// ============================================================================
// Launch
// ============================================================================
extern "C" void kernel_launch(void* const* d_in, const int* in_sizes, int n_in,
                              void* d_out, int out_size) {
    const float* anc = (const float*)d_in[0];   // z_anc      [N, 128]
    const float* pn  = (const float*)d_in[1];   // z_pos_neg  [M, 128]
    int N = in_sizes[0] / DV;
    int M = in_sizes[1] / DV;

    int warps  = N + M;
    int blocks = (warps + 7) / 8;               // 256 threads = 8 warps/block
    prep_kernel<<<blocks, 256>>>(anc, pn, N, M);

    cudaFuncSetAttribute(gemm_kernel, cudaFuncAttributeMaxDynamicSharedMemorySize,
                         SMEM_BYTES);
    dim3 grid(M / TILE, N / TILE);
    gemm_kernel<<<grid, 256, SMEM_BYTES>>>((float*)d_out, N, M);
}

// round 4
// speedup vs baseline: 1.2385x; 1.2385x over previous
#include <cuda_runtime.h>
#include <cuda_bf16.h>
#include <cstdint>

// ============================================================================
// Problem constants (shapes fixed by setup_inputs: N=M=8192, D=128)
// ============================================================================
#define DV      128
#define MAXROWS 8192
#define TILE    128

// bf16 copies + fp32 squared norms (device-global scratch; allowed)
__device__ __nv_bfloat16 g_anc_bf[MAXROWS * DV];
__device__ __nv_bfloat16 g_pn_bf[MAXROWS * DV];
__device__ float         g_anc2[MAXROWS];
__device__ float         g_pn2[MAXROWS];

// ============================================================================
// Kernel 1: fp32 -> bf16 conversion + exact fp32 squared row norms.
// One warp per row (128 floats = 32 lanes x float4).
// ============================================================================
__global__ void prep_kernel(const float* __restrict__ anc, const float* __restrict__ pn,
                            int N, int M) {
    int warp = (blockIdx.x * blockDim.x + threadIdx.x) >> 5;
    int lane = threadIdx.x & 31;
    if (warp >= N + M) return;

    const float* src;
    __nv_bfloat16* dst;
    float* nrm;
    int row;
    if (warp < N) { row = warp;     src = anc + (size_t)row * DV; dst = g_anc_bf + (size_t)row * DV; nrm = g_anc2; }
    else          { row = warp - N; src = pn  + (size_t)row * DV; dst = g_pn_bf  + (size_t)row * DV; nrm = g_pn2;  }

    float4 v = reinterpret_cast<const float4*>(src)[lane];
    float s = v.x * v.x + v.y * v.y + v.z * v.z + v.w * v.w;

    __nv_bfloat162 p0 = __floats2bfloat162_rn(v.x, v.y);
    __nv_bfloat162 p1 = __floats2bfloat162_rn(v.z, v.w);
    reinterpret_cast<__nv_bfloat162*>(dst)[lane * 2 + 0] = p0;
    reinterpret_cast<__nv_bfloat162*>(dst)[lane * 2 + 1] = p1;

    #pragma unroll
    for (int o = 16; o; o >>= 1) s += __shfl_xor_sync(0xFFFFFFFFu, s, o);
    if (lane == 0) nrm[row] = s;
}

// ============================================================================
// Kernel 2: 128x128 output tile per CTA via mma.sync (HMMA bf16, fp32 accum).
//
// R4 changes vs R3 (L1 pipe was 66% = bottleneck):
//  - fragment loads via ldmatrix.m8n8.x4 (48 LDSM/warp vs 192 scalar LDS)
//  - epilogue: direct STG.64 from fragments (32B sectors fully used);
//    the SMEM staging round-trip (128KB/CTA of L1 traffic) is deleted
//  - norms preloaded to registers before the store loop
// ============================================================================
#define SAS  136                             // bf16 elems per SMEM row (128+8 pad)
#define SASB (SAS * 2)                       // 272 bytes per row
static constexpr uint32_t SM_A     = 0;                    // 128*272 = 34816
static constexpr uint32_t SM_B     = 34816;                // 34816
static constexpr uint32_t SM_A2    = 69632;                // 512 B
static constexpr uint32_t SM_B2    = 70144;                // 512 B
static constexpr uint32_t SMEM_BYTES = 70656;

__device__ __forceinline__ uint32_t smem_u32(const void* p) {
    uint32_t a;
    asm("{ .reg .u64 t; cvta.to.shared.u64 t, %1; cvt.u32.u64 %0, t; }" : "=r"(a) : "l"(p));
    return a;
}

__device__ __forceinline__ void ldsm_x4(uint32_t* r, uint32_t addr) {
    asm volatile("ldmatrix.sync.aligned.m8n8.x4.shared.b16 {%0,%1,%2,%3}, [%4];"
                 : "=r"(r[0]), "=r"(r[1]), "=r"(r[2]), "=r"(r[3]) : "r"(addr));
}

__device__ __forceinline__ void mma_bf16(float* c, const uint32_t* a, const uint32_t* b) {
    asm volatile(
        "mma.sync.aligned.m16n8k16.row.col.f32.bf16.bf16.f32 "
        "{%0,%1,%2,%3}, {%4,%5,%6,%7}, {%8,%9}, {%0,%1,%2,%3};"
        : "+f"(c[0]), "+f"(c[1]), "+f"(c[2]), "+f"(c[3])
        : "r"(a[0]), "r"(a[1]), "r"(a[2]), "r"(a[3]), "r"(b[0]), "r"(b[1]));
}

__global__ void __launch_bounds__(256, 2) gemm_kernel(float* __restrict__ out, int N, int M) {
    extern __shared__ char smem[];

    const int tid    = threadIdx.x;
    const int lid    = tid & 31;
    const int wid    = tid >> 5;
    const int warp_m = wid & 3;       // 0..3 -> m offset 32*warp_m
    const int warp_n = wid >> 2;      // 0..1 -> n offset 64*warp_n
    const int tj     = blockIdx.x;    // output col tile (pn rows)
    const int ti     = blockIdx.y;    // output row tile (anc rows)

    // ---- Global -> SMEM: 128 rows x 256 B each, padded stride ----
    {
        const uint4* gA = reinterpret_cast<const uint4*>(g_anc_bf + (size_t)ti * TILE * DV);
        const uint4* gB = reinterpret_cast<const uint4*>(g_pn_bf  + (size_t)tj * TILE * DV);
        int c0 = tid & 15;            // uint4 column 0..15
        int r0 = tid >> 4;            // row 0..15
        #pragma unroll
        for (int it = 0; it < 8; it++) {
            int r = r0 + it * 16;
            uint32_t so = (uint32_t)(r * SASB + c0 * 16);
            *reinterpret_cast<uint4*>(smem + SM_A + so) = gA[r * 16 + c0];
            *reinterpret_cast<uint4*>(smem + SM_B + so) = gB[r * 16 + c0];
        }
        if (tid < 128) {
            reinterpret_cast<float*>(smem + SM_A2)[tid] = g_anc2[ti * TILE + tid];
            reinterpret_cast<float*>(smem + SM_B2)[tid] = g_pn2[tj * TILE + tid];
        }
    }
    __syncthreads();

    // ---- ldmatrix base addresses ----
    // x4 block order for A(mt): b0=(rows 0-7, k-lo16B) b1=(rows 8-15, k-lo)
    //                           b2=(rows 0-7, k-hi16B) b3=(rows 8-15, k-hi)
    //   thread t supplies row (t%8) of block (t/8).
    const uint32_t sbase = smem_u32(smem);
    const int t8 = lid & 7;
    const int bq = lid >> 3;          // block index 0..3
    uint32_t aaddr[2], baddr[4];
    {
        int arow = warp_m * 32 + (bq & 1) * 8 + t8;
        uint32_t ak = (uint32_t)(bq >> 1) * 16;
        aaddr[0] = sbase + SM_A + (uint32_t)arow * SASB + ak;
        aaddr[1] = aaddr[0] + 16u * SASB;
        // B(pair p covers nt=2p,2p+1): b0=(n 0-7,k-lo) b1=(n 0-7,k-hi)
        //                              b2=(n 8-15,k-lo) b3=(n 8-15,k-hi)
        int brow0 = warp_n * 64 + (bq >> 1) * 8 + t8;
        uint32_t bk = (uint32_t)(bq & 1) * 16;
        #pragma unroll
        for (int p = 0; p < 4; p++)
            baddr[p] = sbase + SM_B + (uint32_t)(brow0 + p * 16) * SASB + bk;
    }

    // ---- Mainloop: K = 8 x k16 ----
    float acc[2][8][4];
    #pragma unroll
    for (int mt = 0; mt < 2; mt++)
        #pragma unroll
        for (int nt = 0; nt < 8; nt++)
            #pragma unroll
            for (int e = 0; e < 4; e++) acc[mt][nt][e] = 0.0f;

    #pragma unroll
    for (int ks = 0; ks < 8; ks++) {
        const uint32_t kb = (uint32_t)ks * 32;

        uint32_t afr[2][4];
        ldsm_x4(afr[0], aaddr[0] + kb);
        ldsm_x4(afr[1], aaddr[1] + kb);

        uint32_t bfr[8][2];
        #pragma unroll
        for (int p = 0; p < 4; p++) {
            uint32_t q[4];
            ldsm_x4(q, baddr[p] + kb);
            bfr[2 * p][0]     = q[0]; bfr[2 * p][1]     = q[1];
            bfr[2 * p + 1][0] = q[2]; bfr[2 * p + 1][1] = q[3];
        }

        #pragma unroll
        for (int mt = 0; mt < 2; mt++)
            #pragma unroll
            for (int nt = 0; nt < 8; nt++)
                mma_bf16(acc[mt][nt], afr[mt], bfr[nt]);
    }

    // ---- Epilogue: fuse -sqrt(max(a2+b2-2ab,0)), direct float2 stores ----
    const float* a2s = reinterpret_cast<const float*>(smem + SM_A2);
    const float* b2s = reinterpret_cast<const float*>(smem + SM_B2);

    const int rb = warp_m * 32 + (lid >> 2);          // row base within tile
    const int cb = warp_n * 64 + (lid & 3) * 2;       // col base within tile

    float a2r[2][2];
    #pragma unroll
    for (int mt = 0; mt < 2; mt++) {
        a2r[mt][0] = a2s[rb + mt * 16];
        a2r[mt][1] = a2s[rb + mt * 16 + 8];
    }
    float b2c[8][2];
    #pragma unroll
    for (int nt = 0; nt < 8; nt++) {
        b2c[nt][0] = b2s[cb + nt * 8];
        b2c[nt][1] = b2s[cb + nt * 8 + 1];
    }

    float* outp = out + (size_t)(ti * TILE + rb) * M + tj * TILE + cb;

    #pragma unroll
    for (int mt = 0; mt < 2; mt++) {
        #pragma unroll
        for (int nt = 0; nt < 8; nt++) {
            float v, q;
            float2 s0, s1;
            v = fmaxf(a2r[mt][0] + b2c[nt][0] - 2.0f * acc[mt][nt][0], 0.0f);
            asm("sqrt.approx.f32 %0, %1;" : "=f"(q) : "f"(v));
            s0.x = -q;
            v = fmaxf(a2r[mt][0] + b2c[nt][1] - 2.0f * acc[mt][nt][1], 0.0f);
            asm("sqrt.approx.f32 %0, %1;" : "=f"(q) : "f"(v));
            s0.y = -q;
            v = fmaxf(a2r[mt][1] + b2c[nt][0] - 2.0f * acc[mt][nt][2], 0.0f);
            asm("sqrt.approx.f32 %0, %1;" : "=f"(q) : "f"(v));
            s1.x = -q;
            v = fmaxf(a2r[mt][1] + b2c[nt][1] - 2.0f * acc[mt][nt][3], 0.0f);
            asm("sqrt.approx.f32 %0, %1;" : "=f"(q) : "f"(v));
            s1.y = -q;
            *reinterpret_cast<float2*>(outp + (size_t)(mt * 16) * M + nt * 8)     = s0;
            *reinterpret_cast<float2*>(outp + (size_t)(mt * 16 + 8) * M + nt * 8) = s1;
        }
    }
}

// ============================================================================
// Launch
// ============================================================================
extern "C" void kernel_launch(void* const* d_in, const int* in_sizes, int n_in,
                              void* d_out, int out_size) {
    const float* anc = (const float*)d_in[0];   // z_anc      [N, 128]
    const float* pn  = (const float*)d_in[1];   // z_pos_neg  [M, 128]
    int N = in_sizes[0] / DV;
    int M = in_sizes[1] / DV;

    int warps  = N + M;
    int blocks = (warps + 7) / 8;               // 256 threads = 8 warps/block
    prep_kernel<<<blocks, 256>>>(anc, pn, N, M);

    cudaFuncSetAttribute(gemm_kernel, cudaFuncAttributeMaxDynamicSharedMemorySize,
                         SMEM_BYTES);
    dim3 grid(M / TILE, N / TILE);
    gemm_kernel<<<grid, 256, SMEM_BYTES>>>((float*)d_out, N, M);
}